// round 3
// baseline (speedup 1.0000x reference)
#include <cuda_runtime.h>
#include <cuda_bf16.h>
#include <math.h>

// ---------------- constants ----------------
#define DIMC   384
#define HEADS  8
#define HD     48            // head dim
#define NADLA  343           // 7^3 anchors
#define HWD    14
#define NTOK   2744          // 14^3
#define BATCH  8
#define MTOT   (BATCH*NTOK)  // 21952
#define SCALE  0.14433756729740643f  // 48^-0.5

// ---------------- device scratch ----------------
__device__ float g_q   [(long long)MTOT*DIMC];           // 33.7 MB
__device__ float g_kv  [(long long)MTOT*2*DIMC];         // 67.5 MB
__device__ float g_adla[(long long)BATCH*NADLA*DIMC];    // 4.2 MB
__device__ float g_pb  [(long long)HEADS*NADLA*NTOK];    // 30.1 MB
__device__ float g_ab  [(long long)HEADS*NTOK*NADLA];    // 30.1 MB
__device__ float g_logits[(long long)BATCH*HEADS*NADLA*NTOK]; // 241 MB (reused)
__device__ float g_adlav[(long long)BATCH*HEADS*NADLA*HD];    // 4.2 MB
__device__ float g_attn[(long long)MTOT*DIMC];           // 33.7 MB

static inline int cdiv(int a, int b) { return (a + b - 1) / b; }

// ---------------- generic NN sgemm: C = A[M,K] @ B[K,N] (+bias) ----------------
// batched: blockIdx.z -> (b = z>>3, h = z&7) offsets
__global__ void sgemm_nn(const float* __restrict__ A, const float* __restrict__ B,
                         float* __restrict__ C, const float* __restrict__ bias,
                         int M, int N, int K, int lda, int ldb, int ldc,
                         long long sAb, long long sAh, long long sBb, long long sBh,
                         long long sCb, long long sCh)
{
    int bz = blockIdx.z;
    int bb = bz >> 3, hh = bz & 7;
    A += bb * sAb + hh * sAh;
    B += bb * sBb + hh * sBh;
    C += bb * sCb + hh * sCh;

    __shared__ float As[16][65];
    __shared__ float Bs[16][64];
    int tid = threadIdx.x;
    int tx = tid & 15, ty = tid >> 4;
    int row0 = blockIdx.y * 64, col0 = blockIdx.x * 64;

    float acc[4][4] = {};
    for (int k0 = 0; k0 < K; k0 += 16) {
#pragma unroll
        for (int i = 0; i < 4; i++) {
            int lin = tid + i * 256;
            int r = lin >> 4, kk = lin & 15;
            int gr = row0 + r, gk = k0 + kk;
            As[kk][r] = (gr < M && gk < K) ? A[(long long)gr * lda + gk] : 0.f;
        }
#pragma unroll
        for (int i = 0; i < 4; i++) {
            int lin = tid + i * 256;
            int c = lin & 63, kk = lin >> 6;
            int gc = col0 + c, gk = k0 + kk;
            Bs[kk][c] = (gc < N && gk < K) ? B[(long long)gk * ldb + gc] : 0.f;
        }
        __syncthreads();
#pragma unroll
        for (int kk = 0; kk < 16; kk++) {
            float a[4], b[4];
#pragma unroll
            for (int i = 0; i < 4; i++) a[i] = As[kk][ty * 4 + i];
#pragma unroll
            for (int j = 0; j < 4; j++) b[j] = Bs[kk][tx * 4 + j];
#pragma unroll
            for (int i = 0; i < 4; i++)
#pragma unroll
                for (int j = 0; j < 4; j++) acc[i][j] = fmaf(a[i], b[j], acc[i][j]);
        }
        __syncthreads();
    }
#pragma unroll
    for (int i = 0; i < 4; i++) {
        int gr = row0 + ty * 4 + i;
        if (gr >= M) break;
#pragma unroll
        for (int j = 0; j < 4; j++) {
            int gc = col0 + tx * 4 + j;
            if (gc < N) {
                float v = acc[i][j];
                if (bias) v += bias[gc];
                C[(long long)gr * ldc + gc] = v;
            }
        }
    }
}

// ---------------- NT sgemm, K = 48 fixed: C = alpha*(A @ B^T) + Add ----------------
__global__ void sgemm_nt48(const float* __restrict__ A, const float* __restrict__ B,
                           float* __restrict__ C, const float* __restrict__ Add,
                           int M, int N, int lda, int ldb, int ldc, int ldadd,
                           long long sAb, long long sAh, long long sBb, long long sBh,
                           long long sCbh, long long sAddh, float alpha)
{
    int bz = blockIdx.z;
    int bb = bz >> 3, hh = bz & 7;
    A += bb * sAb + hh * sAh;
    B += bb * sBb + hh * sBh;
    C += (long long)bz * sCbh;
    Add += (long long)hh * sAddh;

    __shared__ float As[64][49];
    __shared__ float Bs[64][49];
    int tid = threadIdx.x;
    int tx = tid & 15, ty = tid >> 4;
    int row0 = blockIdx.y * 64, col0 = blockIdx.x * 64;

#pragma unroll
    for (int i = 0; i < 12; i++) {
        int lin = tid + i * 256;
        int r = lin / 48, kk = lin - r * 48;
        int gr = row0 + r;
        As[r][kk] = (gr < M) ? A[(long long)gr * lda + kk] : 0.f;
        int gc = col0 + r;
        Bs[r][kk] = (gc < N) ? B[(long long)gc * ldb + kk] : 0.f;
    }
    __syncthreads();

    float acc[4][4] = {};
#pragma unroll 8
    for (int kk = 0; kk < 48; kk++) {
        float a[4], b[4];
#pragma unroll
        for (int i = 0; i < 4; i++) a[i] = As[ty * 4 + i][kk];
#pragma unroll
        for (int j = 0; j < 4; j++) b[j] = Bs[tx * 4 + j][kk];
#pragma unroll
        for (int i = 0; i < 4; i++)
#pragma unroll
            for (int j = 0; j < 4; j++) acc[i][j] = fmaf(a[i], b[j], acc[i][j]);
    }
#pragma unroll
    for (int i = 0; i < 4; i++) {
        int gr = row0 + ty * 4 + i;
        if (gr >= M) break;
#pragma unroll
        for (int j = 0; j < 4; j++) {
            int gc = col0 + tx * 4 + j;
            if (gc < N)
                C[(long long)gr * ldc + gc] =
                    alpha * acc[i][j] + Add[(long long)gr * ldadd + gc];
        }
    }
}

// ---------------- pooling: adla[b,a,c] = mean of 2x2x2 block of q ----------------
__global__ void pool_adla(const float* __restrict__ q, float* __restrict__ adla)
{
    int idx = blockIdx.x * 256 + threadIdx.x;
    if (idx >= BATCH * NADLA * DIMC) return;
    int c = idx % DIMC;
    int a = (idx / DIMC) % NADLA;
    int b = idx / (DIMC * NADLA);
    int a1 = a / 49, a2 = (a / 7) % 7, a3 = a % 7;
    float s = 0.f;
#pragma unroll
    for (int i = 0; i < 2; i++)
#pragma unroll
        for (int j = 0; j < 2; j++)
#pragma unroll
            for (int k = 0; k < 2; k++) {
                int n = ((2 * a1 + i) * HWD + (2 * a2 + j)) * HWD + (2 * a3 + k);
                s += q[((long long)(b * NTOK + n)) * DIMC + c];
            }
    adla[idx] = s * 0.125f;
}

// linear-interp helper: out index o (0..13) from 7 inputs
__device__ __forceinline__ void lin_w(int o, int& i0, int& i1, float& w)
{
    float x = 0.5f * o - 0.25f;
    x = fminf(fmaxf(x, 0.f), 6.f);
    i0 = (int)floorf(x);
    i1 = min(i0 + 1, 6);
    w = x - (float)i0;
}

__device__ __forceinline__ float interp3(const float* base, int x, int y, int z)
{
    int x0, x1, y0, y1, z0, z1;
    float wx, wy, wz;
    lin_w(x, x0, x1, wx);
    lin_w(y, y0, y1, wy);
    lin_w(z, z0, z1, wz);
    float c000 = base[x0 * 49 + y0 * 7 + z0], c001 = base[x0 * 49 + y0 * 7 + z1];
    float c010 = base[x0 * 49 + y1 * 7 + z0], c011 = base[x0 * 49 + y1 * 7 + z1];
    float c100 = base[x1 * 49 + y0 * 7 + z0], c101 = base[x1 * 49 + y0 * 7 + z1];
    float c110 = base[x1 * 49 + y1 * 7 + z0], c111 = base[x1 * 49 + y1 * 7 + z1];
    float v0 = (1.f - wy) * ((1.f - wz) * c000 + wz * c001) + wy * ((1.f - wz) * c010 + wz * c011);
    float v1 = (1.f - wy) * ((1.f - wz) * c100 + wz * c101) + wy * ((1.f - wz) * c110 + wz * c111);
    return (1.f - wx) * v0 + wx * v1;
}

// pb[h,a,n] = interp(an_bias)[h,a,n] + ah[h,a,x] + aw[h,a,y] + ad[h,a,z]
__global__ void pb_kernel(const float* __restrict__ an, const float* __restrict__ ah,
                          const float* __restrict__ aw, const float* __restrict__ ad,
                          float* __restrict__ pb)
{
    int idx = blockIdx.x * 256 + threadIdx.x;
    if (idx >= HEADS * NADLA * NTOK) return;
    int n = idx % NTOK;
    int a = (idx / NTOK) % NADLA;
    int h = idx / (NTOK * NADLA);
    int x = n / 196, y = (n / 14) % 14, z = n % 14;
    const float* base = an + ((long long)(h * NADLA + a)) * NADLA;
    float v = interp3(base, x, y, z);
    v += ah[(h * NADLA + a) * HWD + x];
    v += aw[(h * NADLA + a) * HWD + y];
    v += ad[(h * NADLA + a) * HWD + z];
    pb[idx] = v;
}

// ab[h,n,a] = interp(na_bias)[h,a,n] + ha[h,x,a] + wa[h,y,a] + da[h,z,a]
__global__ void ab_kernel(const float* __restrict__ na, const float* __restrict__ ha,
                          const float* __restrict__ wa, const float* __restrict__ da,
                          float* __restrict__ ab)
{
    int idx = blockIdx.x * 256 + threadIdx.x;
    if (idx >= HEADS * NTOK * NADLA) return;
    int a = idx % NADLA;
    int n = (idx / NADLA) % NTOK;
    int h = idx / (NADLA * NTOK);
    int x = n / 196, y = (n / 14) % 14, z = n % 14;
    const float* base = na + ((long long)(h * NADLA + a)) * NADLA;
    float v = interp3(base, x, y, z);
    v += ha[(h * HWD + x) * NADLA + a];
    v += wa[(h * HWD + y) * NADLA + a];
    v += da[(h * HWD + z) * NADLA + a];
    ab[idx] = v;
}

// ---------------- softmax over rows ----------------
__device__ __forceinline__ float warpRedMax(float v)
{
#pragma unroll
    for (int o = 16; o; o >>= 1) v = fmaxf(v, __shfl_xor_sync(0xffffffffu, v, o));
    return v;
}
__device__ __forceinline__ float warpRedSum(float v)
{
#pragma unroll
    for (int o = 16; o; o >>= 1) v += __shfl_xor_sync(0xffffffffu, v, o);
    return v;
}

__global__ void softmax_rows(float* __restrict__ data, int len)
{
    extern __shared__ float s[];
    float* red = s + len;
    float* row = data + (long long)blockIdx.x * len;
    int tid = threadIdx.x, nth = blockDim.x;
    int lane = tid & 31, w = tid >> 5, nw = nth >> 5;

    float m = -3.4e38f;
    for (int i = tid; i < len; i += nth) {
        float v = row[i];
        s[i] = v;
        m = fmaxf(m, v);
    }
    m = warpRedMax(m);
    if (lane == 0) red[w] = m;
    __syncthreads();
    m = (lane < nw) ? red[lane] : -3.4e38f;
    m = warpRedMax(m);
    m = __shfl_sync(0xffffffffu, m, 0);
    __syncthreads();

    float sum = 0.f;
    for (int i = tid; i < len; i += nth) {
        float e = __expf(s[i] - m);
        s[i] = e;
        sum += e;
    }
    sum = warpRedSum(sum);
    if (lane == 0) red[w] = sum;
    __syncthreads();
    sum = (lane < nw) ? red[lane] : 0.f;
    sum = warpRedSum(sum);
    sum = __shfl_sync(0xffffffffu, sum, 0);
    float inv = 1.f / sum;
    for (int i = tid; i < len; i += nth) row[i] = s[i] * inv;
}

// ---------------- depthwise 3x3x3 conv on v, added into attn buffer ----------------
__global__ void dwc_add(const float* __restrict__ kv, const float* __restrict__ w,
                        const float* __restrict__ bias, float* __restrict__ attn)
{
    int blk = blockIdx.x; // b*NTOK + n
    int c = threadIdx.x;  // 0..383
    int b = blk / NTOK, n = blk % NTOK;
    int x = n / 196, y = (n / 14) % 14, z = n % 14;
    float acc = bias[c];
    const float* wc = w + c * 27;
#pragma unroll
    for (int i = -1; i <= 1; i++) {
        int xx = x + i;
        if ((unsigned)xx >= (unsigned)HWD) continue;
#pragma unroll
        for (int j = -1; j <= 1; j++) {
            int yy = y + j;
            if ((unsigned)yy >= (unsigned)HWD) continue;
#pragma unroll
            for (int k = -1; k <= 1; k++) {
                int zz = z + k;
                if ((unsigned)zz >= (unsigned)HWD) continue;
                int nn = (xx * HWD + yy) * HWD + zz;
                acc = fmaf(kv[((long long)(b * NTOK + nn)) * 768 + DIMC + c],
                           wc[(i + 1) * 9 + (j + 1) * 3 + (k + 1)], acc);
            }
        }
    }
    attn[(long long)blk * DIMC + c] += acc;
}

// ---------------- launcher ----------------
extern "C" void kernel_launch(void* const* d_in, const int* in_sizes, int n_in,
                              void* d_out, int out_size)
{
    const float* x     = (const float*)d_in[0];
    const float* Wq    = (const float*)d_in[1];
    const float* Wkv   = (const float*)d_in[2];
    const float* Wproj = (const float*)d_in[3];
    const float* bproj = (const float*)d_in[4];
    const float* dwcw  = (const float*)d_in[5];
    const float* dwcb  = (const float*)d_in[6];
    const float* an    = (const float*)d_in[7];
    const float* na    = (const float*)d_in[8];
    const float* ah    = (const float*)d_in[9];
    const float* aw    = (const float*)d_in[10];
    const float* ad    = (const float*)d_in[11];
    const float* ha    = (const float*)d_in[12];
    const float* wa    = (const float*)d_in[13];
    const float* da    = (const float*)d_in[14];
    float* out = (float*)d_out;

    void* p;
    cudaGetSymbolAddress(&p, g_q);      float* q    = (float*)p;
    cudaGetSymbolAddress(&p, g_kv);     float* kv   = (float*)p;
    cudaGetSymbolAddress(&p, g_adla);   float* adla = (float*)p;
    cudaGetSymbolAddress(&p, g_pb);     float* pb   = (float*)p;
    cudaGetSymbolAddress(&p, g_ab);     float* ab   = (float*)p;
    cudaGetSymbolAddress(&p, g_logits); float* lg   = (float*)p;
    cudaGetSymbolAddress(&p, g_adlav);  float* av   = (float*)p;
    cudaGetSymbolAddress(&p, g_attn);   float* at   = (float*)p;

    // 1) q = x @ Wq   (M=21952, N=384, K=384)
    sgemm_nn<<<dim3(DIMC / 64, MTOT / 64, 1), 256>>>(
        x, Wq, q, nullptr, MTOT, DIMC, DIMC, DIMC, DIMC, DIMC, 0, 0, 0, 0, 0, 0);
    // 2) kv = x @ Wkv (N=768)
    sgemm_nn<<<dim3(768 / 64, MTOT / 64, 1), 256>>>(
        x, Wkv, kv, nullptr, MTOT, 768, DIMC, DIMC, 768, 768, 0, 0, 0, 0, 0, 0);
    // 3) pooled anchors
    pool_adla<<<cdiv(BATCH * NADLA * DIMC, 256), 256>>>(q, adla);
    // 4) positional bias tables
    pb_kernel<<<cdiv(HEADS * NADLA * NTOK, 256), 256>>>(an, ah, aw, ad, pb);
    ab_kernel<<<cdiv(HEADS * NTOK * NADLA, 256), 256>>>(na, ha, wa, da, ab);

    // 5) logits1[bh, a, n] = SCALE * adla_h @ k_h^T + pb[h]
    sgemm_nt48<<<dim3(cdiv(NTOK, 64), cdiv(NADLA, 64), BATCH * HEADS), 256>>>(
        adla, kv, lg, pb,
        NADLA, NTOK, DIMC, 768, NTOK, NTOK,
        (long long)NADLA * DIMC, HD,
        (long long)NTOK * 768, HD,
        (long long)NADLA * NTOK, (long long)NADLA * NTOK, SCALE);
    // 6) softmax over n
    softmax_rows<<<BATCH * HEADS * NADLA, 256, (NTOK + 32) * sizeof(float)>>>(lg, NTOK);
    // 7) adla_v[bh, a, d] = P @ v_h   (M=343, N=48, K=2744)
    sgemm_nn<<<dim3(1, cdiv(NADLA, 64), BATCH * HEADS), 256>>>(
        lg, kv + DIMC, av, nullptr,
        NADLA, HD, NTOK, NTOK, 768, HD,
        (long long)HEADS * NADLA * NTOK, (long long)NADLA * NTOK,
        (long long)NTOK * 768, HD,
        (long long)HEADS * NADLA * HD, (long long)NADLA * HD);

    // 8) logits2[bh, n, a] = SCALE * q_h @ adla_h^T + ab[h]
    sgemm_nt48<<<dim3(cdiv(NADLA, 64), cdiv(NTOK, 64), BATCH * HEADS), 256>>>(
        q, adla, lg, ab,
        NTOK, NADLA, DIMC, DIMC, NADLA, NADLA,
        (long long)NTOK * DIMC, HD,
        (long long)NADLA * DIMC, HD,
        (long long)NTOK * NADLA, (long long)NTOK * NADLA, SCALE);
    // 9) softmax over a
    softmax_rows<<<BATCH * HEADS * NTOK, 128, (NADLA + 32) * sizeof(float)>>>(lg, NADLA);
    // 10) attn[b, n, h*48+d] = P2 @ adla_v  (M=2744, N=48, K=343)
    sgemm_nn<<<dim3(1, cdiv(NTOK, 64), BATCH * HEADS), 256>>>(
        lg, av, at, nullptr,
        NTOK, HD, NADLA, NADLA, HD, DIMC,
        (long long)HEADS * NTOK * NADLA, (long long)NTOK * NADLA,
        (long long)HEADS * NADLA * HD, (long long)NADLA * HD,
        (long long)NTOK * DIMC, HD);

    // 11) depthwise conv on v, accumulate into attn
    dwc_add<<<BATCH * NTOK, DIMC>>>(kv, dwcw, dwcb, at);

    // 12) out = attn @ Wproj + bproj
    sgemm_nn<<<dim3(DIMC / 64, MTOT / 64, 1), 256>>>(
        at, Wproj, out, bproj, MTOT, DIMC, DIMC, DIMC, DIMC, DIMC, 0, 0, 0, 0, 0, 0);
}